// round 12
// baseline (speedup 1.0000x reference)
#include <cuda_runtime.h>
#include <cstdint>

// ---------------------------------------------------------------------------
// SimpleTransformer: ViT-style, weight-shared 6 layers.
// B=64, C=3, H=W=224, P=16 -> 196 patches, PD=768, DIM=1024, HEADS=8, VDIM=128
// Round 7: Round-4 3xTF32 mma.sync GEMM, but 16 warps / 512 threads per CTA
// (warp tile 32x32) for 4 warps/SMSP latency hiding. scores = x(WQ WK^T)x^T
// fusion retained. (tcgen05 unusable: harness compiles compute_103 PTX.)
// ---------------------------------------------------------------------------

#define CB      64
#define NPAT    196
#define PDIM    768
#define DMODEL  1024
#define NHEADS  8
#define VD      128
#define NCLS    1000
#define NDEPTH  6
#define NROWS   (CB * NPAT)          // 12544
#define LN_EPS  1e-5f
#define ATT_SCALE 0.08838834764831845f   // 1/sqrt(128)

// GEMM tiling
#define MT 128
#define NT 128
#define KTILE 32
#define GTHREADS 512
// smem: sa[2][4096] + sb[2][4096] floats = 64KB dynamic
#define GEMM_SMEM (16384 * 4)

// ---------------- scratch (static device globals; no allocs) ----------------
__device__ float g_xp[NROWS * PDIM];                 // patchified+LN'd input
__device__ float g_x [NROWS * DMODEL];               // running activations
__device__ float g_t [NROWS * DMODEL];               // t = LN(x) @ M
__device__ float g_M [DMODEL * DMODEL];              // WQ @ WK^T
__device__ float g_fw[NROWS * DMODEL];               // per-head value transform
__device__ float g_A [(size_t)CB * NPAT * NPAT];     // attention probs
__device__ float g_pool[CB * DMODEL];

// ---------------- tf32 helpers ----------------
__device__ __forceinline__ float tf32r(float x) {
    uint32_t u;
    asm("cvt.rna.tf32.f32 %0, %1;" : "=r"(u) : "f"(x));
    return __uint_as_float(u);
}

__device__ __forceinline__ void mma8(float4& d, const float4& a, const float2& b) {
    uint32_t a0 = __float_as_uint(a.x), a1 = __float_as_uint(a.y);
    uint32_t a2 = __float_as_uint(a.z), a3 = __float_as_uint(a.w);
    uint32_t b0 = __float_as_uint(b.x), b1 = __float_as_uint(b.y);
    asm volatile(
        "mma.sync.aligned.m16n8k8.row.col.f32.tf32.tf32.f32 "
        "{%0,%1,%2,%3},{%4,%5,%6,%7},{%8,%9},{%0,%1,%2,%3};\n"
        : "+f"(d.x), "+f"(d.y), "+f"(d.z), "+f"(d.w)
        : "r"(a0), "r"(a1), "r"(a2), "r"(a3), "r"(b0), "r"(b1));
}

// ---------------- block reductions ----------------
__device__ __forceinline__ void blockReduce2Sum(float& a, float& b) {
    __shared__ float sa[32], sb[32];
    #pragma unroll
    for (int o = 16; o > 0; o >>= 1) {
        a += __shfl_down_sync(0xffffffffu, a, o);
        b += __shfl_down_sync(0xffffffffu, b, o);
    }
    int lane = threadIdx.x & 31, w = threadIdx.x >> 5;
    int nw = blockDim.x >> 5;
    if (lane == 0) { sa[w] = a; sb[w] = b; }
    __syncthreads();
    if (w == 0) {
        a = (lane < nw) ? sa[lane] : 0.f;
        b = (lane < nw) ? sb[lane] : 0.f;
        #pragma unroll
        for (int o = 16; o > 0; o >>= 1) {
            a += __shfl_down_sync(0xffffffffu, a, o);
            b += __shfl_down_sync(0xffffffffu, b, o);
        }
        if (lane == 0) { sa[0] = a; sb[0] = b; }
    }
    __syncthreads();
    a = sa[0]; b = sb[0];
    __syncthreads();
}

__device__ __forceinline__ float blockReduceMax(float v) {
    __shared__ float sm_[32];
    #pragma unroll
    for (int o = 16; o > 0; o >>= 1)
        v = fmaxf(v, __shfl_down_sync(0xffffffffu, v, o));
    int lane = threadIdx.x & 31, w = threadIdx.x >> 5;
    int nw = blockDim.x >> 5;
    if (lane == 0) sm_[w] = v;
    __syncthreads();
    if (w == 0) {
        v = (lane < nw) ? sm_[lane] : -1e30f;
        #pragma unroll
        for (int o = 16; o > 0; o >>= 1)
            v = fmaxf(v, __shfl_down_sync(0xffffffffu, v, o));
        if (lane == 0) sm_[0] = v;
    }
    __syncthreads();
    v = sm_[0];
    __syncthreads();
    return v;
}

__device__ __forceinline__ float blockReduceSum1(float v) {
    __shared__ float ss[32];
    #pragma unroll
    for (int o = 16; o > 0; o >>= 1)
        v += __shfl_down_sync(0xffffffffu, v, o);
    int lane = threadIdx.x & 31, w = threadIdx.x >> 5;
    int nw = blockDim.x >> 5;
    if (lane == 0) ss[w] = v;
    __syncthreads();
    if (w == 0) {
        v = (lane < nw) ? ss[lane] : 0.f;
        #pragma unroll
        for (int o = 16; o > 0; o >>= 1)
            v += __shfl_down_sync(0xffffffffu, v, o);
        if (lane == 0) ss[0] = v;
    }
    __syncthreads();
    v = ss[0];
    __syncthreads();
    return v;
}

// ---------------- patchify + patch layernorm ----------------
__global__ void patchify_ln_kernel(const float* __restrict__ img,
                                   const float* __restrict__ gam,
                                   const float* __restrict__ bet) {
    int row = blockIdx.x;
    int b = row / NPAT, p = row % NPAT;
    int ph = p / 14, pw = p % 14;
    __shared__ float sh[PDIM];
    int t = threadIdx.x;
    float s = 0.f, sq = 0.f;
    for (int i = t; i < PDIM; i += 256) {
        int c  = i % 3;
        int pp = i / 3;
        int p1 = pp >> 4, p2 = pp & 15;
        float v = img[(((size_t)b * 3 + c) * 224 + ph * 16 + p1) * 224 + pw * 16 + p2];
        sh[i] = v;
        s += v; sq += v * v;
    }
    blockReduce2Sum(s, sq);
    float mean = s * (1.f / PDIM);
    float var  = sq * (1.f / PDIM) - mean * mean;
    float inv  = rsqrtf(var + LN_EPS);
    for (int i = t; i < PDIM; i += 256)
        g_xp[(size_t)row * PDIM + i] = (sh[i] - mean) * inv * gam[i] + bet[i];
}

// ---------------- layernorm over DMODEL, optional +pos_emb, in place ----------------
template<bool ADDPOS>
__global__ void ln_kernel(float* __restrict__ x,
                          const float* __restrict__ gam,
                          const float* __restrict__ bet,
                          const float* __restrict__ pos) {
    size_t row = blockIdx.x;
    int t = threadIdx.x;                       // 256 threads * float4 = 1024
    float4 v = ((const float4*)(x + row * DMODEL))[t];
    float s  = v.x + v.y + v.z + v.w;
    float sq = v.x * v.x + v.y * v.y + v.z * v.z + v.w * v.w;
    blockReduce2Sum(s, sq);
    float mean = s * (1.f / DMODEL);
    float var  = sq * (1.f / DMODEL) - mean * mean;
    float inv  = rsqrtf(var + LN_EPS);
    float4 g4 = ((const float4*)gam)[t];
    float4 b4 = ((const float4*)bet)[t];
    float4 o;
    o.x = (v.x - mean) * inv * g4.x + b4.x;
    o.y = (v.y - mean) * inv * g4.y + b4.y;
    o.z = (v.z - mean) * inv * g4.z + b4.z;
    o.w = (v.w - mean) * inv * g4.w + b4.w;
    if (ADDPOS) {
        int n = (int)(row % NPAT);
        float4 p4 = ((const float4*)(pos + (size_t)n * DMODEL))[t];
        o.x += p4.x; o.y += p4.y; o.z += p4.z; o.w += p4.w;
    }
    ((float4*)(x + row * DMODEL))[t] = o;
}

// ---------------- tensor-core GEMM (3xTF32, 16 warps, double-buffered) -------
// C[M,N] = A[M,K] @ B (NN: [K,N], TRANSB: [N,K]) (+bias[N]) (+resid), batch z.
// 512 threads = 16 warps (4 x 4). CTA tile 128x128x32. Warp tile 32x32.
// smem holds fp32 tiles pre-permuted for conflict-free LDS.128/LDS.64
// fragment loads; hi/lo tf32 split happens in registers.
template<bool TRANSB, bool BIAS, bool RESID>
__global__ __launch_bounds__(GTHREADS)
void gemm_tc(const float* __restrict__ A, const float* __restrict__ B,
             const float* __restrict__ bias, const float* __restrict__ resid,
             float* __restrict__ C, int M, int N, int K,
             int lda, int ldb, int ldc,
             long sA, long sB, long sC) {
    extern __shared__ float sm[];
    float* sa = sm;            // [2][4096]
    float* sb = sm + 8192;     // [2][4096]

    long z = blockIdx.z;
    A += z * sA; B += z * sB; C += z * sC;
    if (RESID) resid += z * sC;

    int tid = threadIdx.x;
    int lane = tid & 31, warp = tid >> 5;
    int wm = warp >> 2;        // 0..3  -> 32 rows each
    int wn = warp & 3;         // 0..3  -> 32 cols each
    int m0 = blockIdx.y * MT, n0 = blockIdx.x * NT;

    float4 acc[2][4];
    #pragma unroll
    for (int i = 0; i < 2; i++)
        #pragma unroll
        for (int j = 0; j < 4; j++)
            acc[i][j] = make_float4(0.f, 0.f, 0.f, 0.f);

    int nIter = (K + KTILE - 1) / KTILE;
    float ra[8], rb[8];

    auto loadTiles = [&](int k0) {
        #pragma unroll
        for (int i = 0; i < 8; i++) {       // A tile 128x32 = 4096 elems
            int idx = tid + i * GTHREADS;
            int r = idx >> 5, c = idx & 31;
            int gm = m0 + r, gk = k0 + c;
            ra[i] = (gm < M && gk < K) ? A[(long)gm * lda + gk] : 0.f;
        }
        #pragma unroll
        for (int i = 0; i < 8; i++) {       // B tile 32x128 (logical K x N)
            int idx = tid + i * GTHREADS;
            if (TRANSB) {
                int n = idx >> 5, k = idx & 31;
                int gn = n0 + n, gk = k0 + k;
                rb[i] = (gn < N && gk < K) ? B[(long)gn * ldb + gk] : 0.f;
            } else {
                int k = idx >> 7, n = idx & 127;
                int gk = k0 + k, gn = n0 + n;
                rb[i] = (gk < K && gn < N) ? B[(long)gk * ldb + gn] : 0.f;
            }
        }
    };

    auto storeTiles = [&](int buf) {
        float* pa = sa + buf * 4096;
        float* pb = sb + buf * 4096;
        #pragma unroll
        for (int i = 0; i < 8; i++) {
            int idx = tid + i * GTHREADS;
            int r = idx >> 5, c = idx & 31;
            int mi = r >> 4, rr = r & 15, ki = c >> 3, cc = c & 7;
            int ln_ = ((rr & 7) << 2) | (cc & 3);
            int j   = ((cc >> 2) << 1) | (rr >> 3);
            pa[((mi * 4 + ki) * 32 + ln_) * 4 + j] = ra[i];
        }
        #pragma unroll
        for (int i = 0; i < 8; i++) {
            int idx = tid + i * GTHREADS;
            int k, n;
            if (TRANSB) { n = idx >> 5; k = idx & 31; }
            else        { k = idx >> 7; n = idx & 127; }
            int ni = n >> 3, nn = n & 7, ki = k >> 3, kk = k & 7;
            int ln_ = (nn << 2) | (kk & 3);
            int j   = kk >> 2;
            pb[((ni * 4 + ki) * 32 + ln_) * 2 + j] = rb[i];
        }
    };

    loadTiles(0);
    storeTiles(0);
    __syncthreads();

    for (int it = 0; it < nIter; it++) {
        if (it + 1 < nIter) loadTiles((it + 1) * KTILE);  // LDG covered by compute

        int buf = it & 1;
        const float* pa = sa + buf * 4096;
        const float* pb = sb + buf * 4096;

        #pragma unroll
        for (int ki = 0; ki < 4; ki++) {
            float4 ah[2], al[2];
            float2 bh[4], bl[4];
            #pragma unroll
            for (int mi = 0; mi < 2; mi++) {
                int mig = wm * 2 + mi;
                float4 v = *(const float4*)&pa[((mig * 4 + ki) * 32 + lane) * 4];
                ah[mi].x = tf32r(v.x); al[mi].x = tf32r(v.x - ah[mi].x);
                ah[mi].y = tf32r(v.y); al[mi].y = tf32r(v.y - ah[mi].y);
                ah[mi].z = tf32r(v.z); al[mi].z = tf32r(v.z - ah[mi].z);
                ah[mi].w = tf32r(v.w); al[mi].w = tf32r(v.w - ah[mi].w);
            }
            #pragma unroll
            for (int ni = 0; ni < 4; ni++) {
                int nig = wn * 4 + ni;
                float2 v = *(const float2*)&pb[((nig * 4 + ki) * 32 + lane) * 2];
                bh[ni].x = tf32r(v.x); bl[ni].x = tf32r(v.x - bh[ni].x);
                bh[ni].y = tf32r(v.y); bl[ni].y = tf32r(v.y - bh[ni].y);
            }
            #pragma unroll
            for (int mi = 0; mi < 2; mi++)
                #pragma unroll
                for (int ni = 0; ni < 4; ni++) {
                    mma8(acc[mi][ni], al[mi], bh[ni]);
                    mma8(acc[mi][ni], ah[mi], bl[ni]);
                    mma8(acc[mi][ni], ah[mi], bh[ni]);
                }
        }

        if (it + 1 < nIter) storeTiles(buf ^ 1);
        __syncthreads();
    }

    // epilogue
    int g = lane >> 2, t4 = lane & 3;
    #pragma unroll
    for (int mi = 0; mi < 2; mi++) {
        int row = m0 + (wm * 2 + mi) * 16 + g;
        #pragma unroll
        for (int ni = 0; ni < 4; ni++) {
            int col = n0 + (wn * 4 + ni) * 8 + t4 * 2;
            float4 v = acc[mi][ni];
            if (BIAS) {
                if (col < N)     { v.x += bias[col];     v.z += bias[col]; }
                if (col + 1 < N) { v.y += bias[col + 1]; v.w += bias[col + 1]; }
            }
            if (row < M) {
                long o = (long)row * ldc + col;
                if (col < N)     C[o]     = RESID ? v.x + resid[o]     : v.x;
                if (col + 1 < N) C[o + 1] = RESID ? v.y + resid[o + 1] : v.y;
            }
            if (row + 8 < M) {
                long o = (long)(row + 8) * ldc + col;
                if (col < N)     C[o]     = RESID ? v.z + resid[o]     : v.z;
                if (col + 1 < N) C[o + 1] = RESID ? v.w + resid[o + 1] : v.w;
            }
        }
    }
}

// ---------------- softmax over 196 columns (scale folded in) ----------------
__global__ void softmax_kernel(float* __restrict__ S) {
    size_t row = blockIdx.x;
    float* p = S + row * NPAT;
    int t = threadIdx.x;                    // 256
    float v = (t < NPAT) ? p[t] * ATT_SCALE : -1e30f;
    float m = blockReduceMax(v);
    float e = (t < NPAT) ? __expf(v - m) : 0.f;
    float s = blockReduceSum1(e);
    if (t < NPAT) p[t] = e / s;
}

// ---------------- mean pool over patches ----------------
__global__ void pool_kernel() {
    int i = blockIdx.x * 256 + threadIdx.x;     // b*DMODEL + d
    if (i >= CB * DMODEL) return;
    int b = i / DMODEL, d = i % DMODEL;
    const float* p = g_x + (size_t)b * NPAT * DMODEL + d;
    float s = 0.f;
    for (int n = 0; n < NPAT; n++) s += p[(size_t)n * DMODEL];
    g_pool[i] = s * (1.f / NPAT);
}

// ---------------- launch ----------------
extern "C" void kernel_launch(void* const* d_in, const int* in_sizes, int n_in,
                              void* d_out, int out_size) {
    const float* image   = (const float*)d_in[0];
    const float* pos_emb = (const float*)d_in[1];
    const float* ln_p_g  = (const float*)d_in[2];
    const float* ln_p_b  = (const float*)d_in[3];
    const float* W_emb   = (const float*)d_in[4];
    const float* b_emb   = (const float*)d_in[5];
    const float* ln_e_g  = (const float*)d_in[6];
    const float* ln_e_b  = (const float*)d_in[7];
    const float* WV      = (const float*)d_in[8];
    const float* WK      = (const float*)d_in[9];
    const float* WQ      = (const float*)d_in[10];
    const float* ln_g    = (const float*)d_in[11];
    const float* ln_b    = (const float*)d_in[12];
    const float* W_last  = (const float*)d_in[13];
    const float* b_last  = (const float*)d_in[14];
    float* out = (float*)d_out;

    float *xp, *x, *t, *Mw, *fw, *A, *pool;
    cudaGetSymbolAddress((void**)&xp,   g_xp);
    cudaGetSymbolAddress((void**)&x,    g_x);
    cudaGetSymbolAddress((void**)&t,    g_t);
    cudaGetSymbolAddress((void**)&Mw,   g_M);
    cudaGetSymbolAddress((void**)&fw,   g_fw);
    cudaGetSymbolAddress((void**)&A,    g_A);
    cudaGetSymbolAddress((void**)&pool, g_pool);

    cudaFuncSetAttribute(gemm_tc<false, true,  false>,
                         cudaFuncAttributeMaxDynamicSharedMemorySize, GEMM_SMEM);
    cudaFuncSetAttribute(gemm_tc<false, false, false>,
                         cudaFuncAttributeMaxDynamicSharedMemorySize, GEMM_SMEM);
    cudaFuncSetAttribute(gemm_tc<true,  false, false>,
                         cudaFuncAttributeMaxDynamicSharedMemorySize, GEMM_SMEM);
    cudaFuncSetAttribute(gemm_tc<false, false, true>,
                         cudaFuncAttributeMaxDynamicSharedMemorySize, GEMM_SMEM);

    // 0) M = WQ @ WK^T
    gemm_tc<true, false, false><<<dim3(8, 8, 1), GTHREADS, GEMM_SMEM>>>(
        WQ, WK, nullptr, nullptr, Mw, DMODEL, DMODEL, DMODEL, DMODEL, DMODEL, DMODEL, 0, 0, 0);

    // 1) patchify + LN_p
    patchify_ln_kernel<<<NROWS, 256>>>(image, ln_p_g, ln_p_b);

    // 2) embed GEMM: [12544,768]@[768,1024] + b_emb
    gemm_tc<false, true, false><<<dim3(8, 98, 1), GTHREADS, GEMM_SMEM>>>(
        xp, W_emb, b_emb, nullptr, x, NROWS, DMODEL, PDIM, PDIM, DMODEL, DMODEL, 0, 0, 0);

    // 3) LN_e + pos_emb (in place)
    ln_kernel<true><<<NROWS, 256>>>(x, ln_e_g, ln_e_b, pos_emb);

    // 4) transformer layers (weight shared)
    for (int l = 0; l < NDEPTH; l++) {
        // x <- LN(x)  (residual uses the normed x, matching reference)
        ln_kernel<false><<<NROWS, 256>>>(x, ln_g, ln_b, nullptr);

        // t = x @ M   (replaces q AND k GEMMs)
        gemm_tc<false, false, false><<<dim3(8, 98, 1), GTHREADS, GEMM_SMEM>>>(
            x, Mw, nullptr, nullptr, t, NROWS, DMODEL, DMODEL, DMODEL, DMODEL, DMODEL, 0, 0, 0);

        // fw: per-head value transform == [12544*8,128]@[128,128]
        gemm_tc<false, false, false><<<dim3(1, 784, 1), GTHREADS, GEMM_SMEM>>>(
            x, WV, nullptr, nullptr, fw, NROWS * NHEADS, VD, VD, VD, VD, VD, 0, 0, 0);

        // scores: per-batch [196,1024]@[196,1024]^T -> [196,196]; A = t @ x^T
        gemm_tc<true, false, false><<<dim3(2, 2, CB), GTHREADS, GEMM_SMEM>>>(
            t, x, nullptr, nullptr, A, NPAT, NPAT, DMODEL, DMODEL, DMODEL, NPAT,
            (long)NPAT * DMODEL, (long)NPAT * DMODEL, (long)NPAT * NPAT);

        // softmax rows (scale folded in)
        softmax_kernel<<<NROWS, 256>>>(A);

        // x = A@fw + x   (TAU = 1)
        gemm_tc<false, false, true><<<dim3(8, 2, CB), GTHREADS, GEMM_SMEM>>>(
            A, fw, nullptr, x, x, NPAT, DMODEL, NPAT, NPAT, DMODEL, DMODEL,
            (long)NPAT * NPAT, (long)NPAT * DMODEL, (long)NPAT * DMODEL);
    }

    // 5) mean pool
    pool_kernel<<<(CB * DMODEL + 255) / 256, 256>>>();

    // 6) classifier: [64,1024]@[1024,1000] + b_last
    gemm_tc<false, true, false><<<dim3(8, 1, 1), GTHREADS, GEMM_SMEM>>>(
        pool, W_last, b_last, nullptr, out, CB, NCLS, DMODEL, DMODEL, NCLS, NCLS, 0, 0, 0);
}

// round 14
// speedup vs baseline: 1.0171x; 1.0171x over previous
#include <cuda_runtime.h>
#include <cstdint>

// SimpleTransformer ViT, weight-shared 6 layers. Round 13:
// Round-4 3xTF32 mma.sync GEMM + conflict-free smem:
//  - A perm layout with ki-XOR store swizzle (stores 4-way -> 2-way)
//  - B (NN) plain [k][136] padded tile (stores + frag loads conflict-free)
//  - mask-based tf32 hi/lo split (no CVT; AND on alu pipe + SUB on fma pipe)
// scores = x (WQ WK^T) x^T fusion retained.

#define CB      64
#define NPAT    196
#define PDIM    768
#define DMODEL  1024
#define NHEADS  8
#define VD      128
#define NCLS    1000
#define NDEPTH  6
#define NROWS   (CB * NPAT)
#define LN_EPS  1e-5f
#define ATT_SCALE 0.08838834764831845f

#define MT 128
#define NT 128
#define KTILE 32
// smem floats: A 2*4096 + B 2*4352 = 16896 floats = 67584 B
#define GEMM_SMEM ((8192 + 8704) * 4)

__device__ float g_xp[NROWS * PDIM];
__device__ float g_x [NROWS * DMODEL];
__device__ float g_t [NROWS * DMODEL];
__device__ float g_M [DMODEL * DMODEL];
__device__ float g_fw[NROWS * DMODEL];
__device__ float g_A [(size_t)CB * NPAT * NPAT];
__device__ float g_pool[CB * DMODEL];

__device__ __forceinline__ float maskhi(float x) {
    return __uint_as_float(__float_as_uint(x) & 0xFFFFE000u);
}

__device__ __forceinline__ void mma8(float4& d, const float4& a, const float2& b) {
    uint32_t a0 = __float_as_uint(a.x), a1 = __float_as_uint(a.y);
    uint32_t a2 = __float_as_uint(a.z), a3 = __float_as_uint(a.w);
    uint32_t b0 = __float_as_uint(b.x), b1 = __float_as_uint(b.y);
    asm volatile(
        "mma.sync.aligned.m16n8k8.row.col.f32.tf32.tf32.f32 "
        "{%0,%1,%2,%3},{%4,%5,%6,%7},{%8,%9},{%0,%1,%2,%3};\n"
        : "+f"(d.x), "+f"(d.y), "+f"(d.z), "+f"(d.w)
        : "r"(a0), "r"(a1), "r"(a2), "r"(a3), "r"(b0), "r"(b1));
}

__device__ __forceinline__ void blockReduce2Sum(float& a, float& b) {
    __shared__ float sa[32], sb[32];
    #pragma unroll
    for (int o = 16; o > 0; o >>= 1) {
        a += __shfl_down_sync(0xffffffffu, a, o);
        b += __shfl_down_sync(0xffffffffu, b, o);
    }
    int lane = threadIdx.x & 31, w = threadIdx.x >> 5;
    int nw = blockDim.x >> 5;
    if (lane == 0) { sa[w] = a; sb[w] = b; }
    __syncthreads();
    if (w == 0) {
        a = (lane < nw) ? sa[lane] : 0.f;
        b = (lane < nw) ? sb[lane] : 0.f;
        #pragma unroll
        for (int o = 16; o > 0; o >>= 1) {
            a += __shfl_down_sync(0xffffffffu, a, o);
            b += __shfl_down_sync(0xffffffffu, b, o);
        }
        if (lane == 0) { sa[0] = a; sb[0] = b; }
    }
    __syncthreads();
    a = sa[0]; b = sb[0];
    __syncthreads();
}

__device__ __forceinline__ float blockReduceMax(float v) {
    __shared__ float sm_[32];
    #pragma unroll
    for (int o = 16; o > 0; o >>= 1)
        v = fmaxf(v, __shfl_down_sync(0xffffffffu, v, o));
    int lane = threadIdx.x & 31, w = threadIdx.x >> 5;
    int nw = blockDim.x >> 5;
    if (lane == 0) sm_[w] = v;
    __syncthreads();
    if (w == 0) {
        v = (lane < nw) ? sm_[lane] : -1e30f;
        #pragma unroll
        for (int o = 16; o > 0; o >>= 1)
            v = fmaxf(v, __shfl_down_sync(0xffffffffu, v, o));
        if (lane == 0) sm_[0] = v;
    }
    __syncthreads();
    v = sm_[0];
    __syncthreads();
    return v;
}

__device__ __forceinline__ float blockReduceSum1(float v) {
    __shared__ float ss[32];
    #pragma unroll
    for (int o = 16; o > 0; o >>= 1)
        v += __shfl_down_sync(0xffffffffu, v, o);
    int lane = threadIdx.x & 31, w = threadIdx.x >> 5;
    int nw = blockDim.x >> 5;
    if (lane == 0) ss[w] = v;
    __syncthreads();
    if (w == 0) {
        v = (lane < nw) ? ss[lane] : 0.f;
        #pragma unroll
        for (int o = 16; o > 0; o >>= 1)
            v += __shfl_down_sync(0xffffffffu, v, o);
        if (lane == 0) ss[0] = v;
    }
    __syncthreads();
    v = ss[0];
    __syncthreads();
    return v;
}

__global__ void patchify_ln_kernel(const float* __restrict__ img,
                                   const float* __restrict__ gam,
                                   const float* __restrict__ bet) {
    int row = blockIdx.x;
    int b = row / NPAT, p = row % NPAT;
    int ph = p / 14, pw = p % 14;
    __shared__ float sh[PDIM];
    int t = threadIdx.x;
    float s = 0.f, sq = 0.f;
    for (int i = t; i < PDIM; i += 256) {
        int c  = i % 3;
        int pp = i / 3;
        int p1 = pp >> 4, p2 = pp & 15;
        float v = img[(((size_t)b * 3 + c) * 224 + ph * 16 + p1) * 224 + pw * 16 + p2];
        sh[i] = v;
        s += v; sq += v * v;
    }
    blockReduce2Sum(s, sq);
    float mean = s * (1.f / PDIM);
    float var  = sq * (1.f / PDIM) - mean * mean;
    float inv  = rsqrtf(var + LN_EPS);
    for (int i = t; i < PDIM; i += 256)
        g_xp[(size_t)row * PDIM + i] = (sh[i] - mean) * inv * gam[i] + bet[i];
}

template<bool ADDPOS>
__global__ void ln_kernel(float* __restrict__ x,
                          const float* __restrict__ gam,
                          const float* __restrict__ bet,
                          const float* __restrict__ pos) {
    size_t row = blockIdx.x;
    int t = threadIdx.x;
    float4 v = ((const float4*)(x + row * DMODEL))[t];
    float s  = v.x + v.y + v.z + v.w;
    float sq = v.x * v.x + v.y * v.y + v.z * v.z + v.w * v.w;
    blockReduce2Sum(s, sq);
    float mean = s * (1.f / DMODEL);
    float var  = sq * (1.f / DMODEL) - mean * mean;
    float inv  = rsqrtf(var + LN_EPS);
    float4 g4 = ((const float4*)gam)[t];
    float4 b4 = ((const float4*)bet)[t];
    float4 o;
    o.x = (v.x - mean) * inv * g4.x + b4.x;
    o.y = (v.y - mean) * inv * g4.y + b4.y;
    o.z = (v.z - mean) * inv * g4.z + b4.z;
    o.w = (v.w - mean) * inv * g4.w + b4.w;
    if (ADDPOS) {
        int n = (int)(row % NPAT);
        float4 p4 = ((const float4*)(pos + (size_t)n * DMODEL))[t];
        o.x += p4.x; o.y += p4.y; o.z += p4.z; o.w += p4.w;
    }
    ((float4*)(x + row * DMODEL))[t] = o;
}

// 3xTF32 GEMM. 256 thr = 8 warps (2x4). CTA 128x128x32, warp 64x32.
template<bool TRANSB, bool BIAS, bool RESID>
__global__ __launch_bounds__(256)
void gemm_tc(const float* __restrict__ A, const float* __restrict__ B,
             const float* __restrict__ bias, const float* __restrict__ resid,
             float* __restrict__ C, int M, int N, int K,
             int lda, int ldb, int ldc,
             long sA, long sB, long sC) {
    extern __shared__ float sm[];
    float* sa = sm;            // [2][4096] A: perm + ki-xor swizzle
    float* sb = sm + 8192;     // [2][4352] B: NN [k][136] / TB perm

    long z = blockIdx.z;
    A += z * sA; B += z * sB; C += z * sC;
    if (RESID) resid += z * sC;

    int tid = threadIdx.x;
    int lane = tid & 31, warp = tid >> 5;
    int wm = warp >> 2;
    int wn = warp & 3;
    int m0 = blockIdx.y * MT, n0 = blockIdx.x * NT;

    float4 acc[4][4];
    #pragma unroll
    for (int i = 0; i < 4; i++)
        #pragma unroll
        for (int j = 0; j < 4; j++)
            acc[i][j] = make_float4(0.f, 0.f, 0.f, 0.f);

    int nIter = (K + KTILE - 1) / KTILE;
    float ra[16], rb[16];

    auto loadTiles = [&](int k0) {
        #pragma unroll
        for (int i = 0; i < 16; i++) {       // A tile 128x32
            int idx = tid + i * 256;
            int r = idx >> 5, c = idx & 31;
            int gm = m0 + r, gk = k0 + c;
            ra[i] = (gm < M && gk < K) ? A[(long)gm * lda + gk] : 0.f;
        }
        #pragma unroll
        for (int i = 0; i < 16; i++) {       // B tile 32x128 logical KxN
            int idx = tid + i * 256;
            if (TRANSB) {
                int n = idx >> 5, k = idx & 31;
                int gn = n0 + n, gk = k0 + k;
                rb[i] = (gn < N && gk < K) ? B[(long)gn * ldb + gk] : 0.f;
            } else {
                int k = idx >> 7, n = idx & 127;
                int gk = k0 + k, gn = n0 + n;
                rb[i] = (gk < K && gn < N) ? B[(long)gk * ldb + gn] : 0.f;
            }
        }
    };

    auto storeTiles = [&](int buf) {
        float* pa = sa + buf * 4096;
        float* pb = sb + buf * 4352;
        #pragma unroll
        for (int i = 0; i < 16; i++) {
            int idx = tid + i * 256;
            int r = idx >> 5, c = idx & 31;
            int mi = r >> 4, rr = r & 15, ki = c >> 3, cc = c & 7;
            int ln_ = ((((rr & 7) << 2) | (cc & 3)) ^ ((ki & 1) << 2));
            int j   = ((cc >> 2) << 1) | (rr >> 3);
            pa[((mi * 4 + ki) * 32 + ln_) * 4 + j] = ra[i];
        }
        #pragma unroll
        for (int i = 0; i < 16; i++) {
            int idx = tid + i * 256;
            if (TRANSB) {
                int n = idx >> 5, k = idx & 31;
                int ni = n >> 3, nn = n & 7, ki = k >> 3, kk = k & 7;
                int ln_ = (nn << 2) | (kk & 3);
                int j   = kk >> 2;
                pb[((ni * 4 + ki) * 32 + ln_) * 2 + j] = rb[i];
            } else {
                int k = idx >> 7, n = idx & 127;
                pb[k * 136 + n] = rb[i];   // conflict-free: 32 consecutive words
            }
        }
    };

    loadTiles(0);
    storeTiles(0);
    __syncthreads();

    for (int it = 0; it < nIter; it++) {
        if (it + 1 < nIter) loadTiles((it + 1) * KTILE);

        int buf = it & 1;
        const float* pa = sa + buf * 4096;
        const float* pb = sb + buf * 4352;

        #pragma unroll
        for (int ki = 0; ki < 4; ki++) {
            float4 ah[4], al[4];
            float2 bh[4], bl[4];
            int lnA = lane ^ ((ki & 1) << 2);
            #pragma unroll
            for (int mi = 0; mi < 4; mi++) {
                int mig = wm * 4 + mi;
                float4 v = *(const float4*)&pa[((mig * 4 + ki) * 32 + lnA) * 4];
                ah[mi].x = maskhi(v.x); al[mi].x = v.x - ah[mi].x;
                ah[mi].y = maskhi(v.y); al[mi].y = v.y - ah[mi].y;
                ah[mi].z = maskhi(v.z); al[mi].z = v.z - ah[mi].z;
                ah[mi].w = maskhi(v.w); al[mi].w = v.w - ah[mi].w;
            }
            #pragma unroll
            for (int ni = 0; ni < 4; ni++) {
                int nig = wn * 4 + ni;
                float2 v;
                if (TRANSB) {
                    v = *(const float2*)&pb[((nig * 4 + ki) * 32 + lane) * 2];
                } else {
                    int krow = ki * 8 + (lane & 3);
                    int n = nig * 8 + (lane >> 2);
                    v.x = pb[krow * 136 + n];
                    v.y = pb[(krow + 4) * 136 + n];
                }
                bh[ni].x = maskhi(v.x); bl[ni].x = v.x - bh[ni].x;
                bh[ni].y = maskhi(v.y); bl[ni].y = v.y - bh[ni].y;
            }
            #pragma unroll
            for (int mi = 0; mi < 4; mi++)
                #pragma unroll
                for (int ni = 0; ni < 4; ni++) {
                    mma8(acc[mi][ni], al[mi], bh[ni]);
                    mma8(acc[mi][ni], ah[mi], bl[ni]);
                    mma8(acc[mi][ni], ah[mi], bh[ni]);
                }
        }

        if (it + 1 < nIter) storeTiles(buf ^ 1);
        __syncthreads();
    }

    int g = lane >> 2, t4 = lane & 3;
    #pragma unroll
    for (int mi = 0; mi < 4; mi++) {
        int row = m0 + (wm * 4 + mi) * 16 + g;
        #pragma unroll
        for (int ni = 0; ni < 4; ni++) {
            int col = n0 + (wn * 4 + ni) * 8 + t4 * 2;
            float4 v = acc[mi][ni];
            if (BIAS) {
                if (col < N)     { v.x += bias[col];     v.z += bias[col]; }
                if (col + 1 < N) { v.y += bias[col + 1]; v.w += bias[col + 1]; }
            }
            if (row < M) {
                long o = (long)row * ldc + col;
                if (col < N)     C[o]     = RESID ? v.x + resid[o]     : v.x;
                if (col + 1 < N) C[o + 1] = RESID ? v.y + resid[o + 1] : v.y;
            }
            if (row + 8 < M) {
                long o = (long)(row + 8) * ldc + col;
                if (col < N)     C[o]     = RESID ? v.z + resid[o]     : v.z;
                if (col + 1 < N) C[o + 1] = RESID ? v.w + resid[o + 1] : v.w;
            }
        }
    }
}

__global__ void softmax_kernel(float* __restrict__ S) {
    size_t row = blockIdx.x;
    float* p = S + row * NPAT;
    int t = threadIdx.x;
    float v = (t < NPAT) ? p[t] * ATT_SCALE : -1e30f;
    float m = blockReduceMax(v);
    float e = (t < NPAT) ? __expf(v - m) : 0.f;
    float s = blockReduceSum1(e);
    if (t < NPAT) p[t] = e / s;
}

__global__ void pool_kernel() {
    int i = blockIdx.x * 256 + threadIdx.x;
    if (i >= CB * DMODEL) return;
    int b = i / DMODEL, d = i % DMODEL;
    const float* p = g_x + (size_t)b * NPAT * DMODEL + d;
    float s = 0.f;
    for (int n = 0; n < NPAT; n++) s += p[(size_t)n * DMODEL];
    g_pool[i] = s * (1.f / NPAT);
}

extern "C" void kernel_launch(void* const* d_in, const int* in_sizes, int n_in,
                              void* d_out, int out_size) {
    const float* image   = (const float*)d_in[0];
    const float* pos_emb = (const float*)d_in[1];
    const float* ln_p_g  = (const float*)d_in[2];
    const float* ln_p_b  = (const float*)d_in[3];
    const float* W_emb   = (const float*)d_in[4];
    const float* b_emb   = (const float*)d_in[5];
    const float* ln_e_g  = (const float*)d_in[6];
    const float* ln_e_b  = (const float*)d_in[7];
    const float* WV      = (const float*)d_in[8];
    const float* WK      = (const float*)d_in[9];
    const float* WQ      = (const float*)d_in[10];
    const float* ln_g    = (const float*)d_in[11];
    const float* ln_b    = (const float*)d_in[12];
    const float* W_last  = (const float*)d_in[13];
    const float* b_last  = (const float*)d_in[14];
    float* out = (float*)d_out;

    float *xp, *x, *t, *Mw, *fw, *A, *pool;
    cudaGetSymbolAddress((void**)&xp,   g_xp);
    cudaGetSymbolAddress((void**)&x,    g_x);
    cudaGetSymbolAddress((void**)&t,    g_t);
    cudaGetSymbolAddress((void**)&Mw,   g_M);
    cudaGetSymbolAddress((void**)&fw,   g_fw);
    cudaGetSymbolAddress((void**)&A,    g_A);
    cudaGetSymbolAddress((void**)&pool, g_pool);

    cudaFuncSetAttribute(gemm_tc<false, true,  false>,
                         cudaFuncAttributeMaxDynamicSharedMemorySize, GEMM_SMEM);
    cudaFuncSetAttribute(gemm_tc<false, false, false>,
                         cudaFuncAttributeMaxDynamicSharedMemorySize, GEMM_SMEM);
    cudaFuncSetAttribute(gemm_tc<true,  false, false>,
                         cudaFuncAttributeMaxDynamicSharedMemorySize, GEMM_SMEM);
    cudaFuncSetAttribute(gemm_tc<false, false, true>,
                         cudaFuncAttributeMaxDynamicSharedMemorySize, GEMM_SMEM);

    // 0) M = WQ @ WK^T
    gemm_tc<true, false, false><<<dim3(8, 8, 1), 256, GEMM_SMEM>>>(
        WQ, WK, nullptr, nullptr, Mw, DMODEL, DMODEL, DMODEL, DMODEL, DMODEL, DMODEL, 0, 0, 0);

    // 1) patchify + LN_p
    patchify_ln_kernel<<<NROWS, 256>>>(image, ln_p_g, ln_p_b);

    // 2) embed
    gemm_tc<false, true, false><<<dim3(8, 98, 1), 256, GEMM_SMEM>>>(
        xp, W_emb, b_emb, nullptr, x, NROWS, DMODEL, PDIM, PDIM, DMODEL, DMODEL, 0, 0, 0);

    // 3) LN_e + pos
    ln_kernel<true><<<NROWS, 256>>>(x, ln_e_g, ln_e_b, pos_emb);

    for (int l = 0; l < NDEPTH; l++) {
        ln_kernel<false><<<NROWS, 256>>>(x, ln_g, ln_b, nullptr);

        // t = x @ M  (fused q,k)
        gemm_tc<false, false, false><<<dim3(8, 98, 1), 256, GEMM_SMEM>>>(
            x, Mw, nullptr, nullptr, t, NROWS, DMODEL, DMODEL, DMODEL, DMODEL, DMODEL, 0, 0, 0);

        // fw per-head value transform
        gemm_tc<false, false, false><<<dim3(1, 784, 1), 256, GEMM_SMEM>>>(
            x, WV, nullptr, nullptr, fw, NROWS * NHEADS, VD, VD, VD, VD, VD, 0, 0, 0);

        // scores A = t @ x^T per batch
        gemm_tc<true, false, false><<<dim3(2, 2, CB), 256, GEMM_SMEM>>>(
            t, x, nullptr, nullptr, A, NPAT, NPAT, DMODEL, DMODEL, DMODEL, NPAT,
            (long)NPAT * DMODEL, (long)NPAT * DMODEL, (long)NPAT * NPAT);

        softmax_kernel<<<NROWS, 256>>>(A);

        // x = A @ fw + x
        gemm_tc<false, false, true><<<dim3(8, 2, CB), 256, GEMM_SMEM>>>(
            A, fw, nullptr, x, x, NPAT, DMODEL, NPAT, NPAT, DMODEL, DMODEL,
            (long)NPAT * NPAT, (long)NPAT * DMODEL, (long)NPAT * DMODEL);
    }

    pool_kernel<<<(CB * DMODEL + 255) / 256, 256>>>();

    gemm_tc<false, true, false><<<dim3(8, 1, 1), 256, GEMM_SMEM>>>(
        pool, W_last, b_last, nullptr, out, CB, NCLS, DMODEL, DMODEL, NCLS, NCLS, 0, 0, 0);
}

// round 17
// speedup vs baseline: 1.0602x; 1.0424x over previous
#include <cuda_runtime.h>
#include <cstdint>

// ---------------------------------------------------------------------------
// SimpleTransformer: ViT-style, weight-shared 6 layers.
// Round 15: GEMM kernel identical to the Round-4 champion (3xTF32 mma.sync,
// double-buffered permuted smem). NEW: dual-stream fork-join inside graph
// capture — fw-GEMM runs concurrently with t/scores/softmax; M-precompute
// overlaps patchify/embed. Fills wave-quantization tails.
// ---------------------------------------------------------------------------

#define CB      64
#define NPAT    196
#define PDIM    768
#define DMODEL  1024
#define NHEADS  8
#define VD      128
#define NCLS    1000
#define NDEPTH  6
#define NROWS   (CB * NPAT)          // 12544
#define LN_EPS  1e-5f
#define ATT_SCALE 0.08838834764831845f   // 1/sqrt(128)

#define MT 128
#define NT 128
#define KTILE 32
#define GEMM_SMEM (16384 * 4)

__device__ float g_xp[NROWS * PDIM];
__device__ float g_x [NROWS * DMODEL];
__device__ float g_t [NROWS * DMODEL];
__device__ float g_M [DMODEL * DMODEL];
__device__ float g_fw[NROWS * DMODEL];
__device__ float g_A [(size_t)CB * NPAT * NPAT];
__device__ float g_pool[CB * DMODEL];

__device__ __forceinline__ float tf32r(float x) {
    uint32_t u;
    asm("cvt.rna.tf32.f32 %0, %1;" : "=r"(u) : "f"(x));
    return __uint_as_float(u);
}

__device__ __forceinline__ void mma8(float4& d, const float4& a, const float2& b) {
    uint32_t a0 = __float_as_uint(a.x), a1 = __float_as_uint(a.y);
    uint32_t a2 = __float_as_uint(a.z), a3 = __float_as_uint(a.w);
    uint32_t b0 = __float_as_uint(b.x), b1 = __float_as_uint(b.y);
    asm volatile(
        "mma.sync.aligned.m16n8k8.row.col.f32.tf32.tf32.f32 "
        "{%0,%1,%2,%3},{%4,%5,%6,%7},{%8,%9},{%0,%1,%2,%3};\n"
        : "+f"(d.x), "+f"(d.y), "+f"(d.z), "+f"(d.w)
        : "r"(a0), "r"(a1), "r"(a2), "r"(a3), "r"(b0), "r"(b1));
}

__device__ __forceinline__ void blockReduce2Sum(float& a, float& b) {
    __shared__ float sa[32], sb[32];
    #pragma unroll
    for (int o = 16; o > 0; o >>= 1) {
        a += __shfl_down_sync(0xffffffffu, a, o);
        b += __shfl_down_sync(0xffffffffu, b, o);
    }
    int lane = threadIdx.x & 31, w = threadIdx.x >> 5;
    int nw = blockDim.x >> 5;
    if (lane == 0) { sa[w] = a; sb[w] = b; }
    __syncthreads();
    if (w == 0) {
        a = (lane < nw) ? sa[lane] : 0.f;
        b = (lane < nw) ? sb[lane] : 0.f;
        #pragma unroll
        for (int o = 16; o > 0; o >>= 1) {
            a += __shfl_down_sync(0xffffffffu, a, o);
            b += __shfl_down_sync(0xffffffffu, b, o);
        }
        if (lane == 0) { sa[0] = a; sb[0] = b; }
    }
    __syncthreads();
    a = sa[0]; b = sb[0];
    __syncthreads();
}

__device__ __forceinline__ float blockReduceMax(float v) {
    __shared__ float sm_[32];
    #pragma unroll
    for (int o = 16; o > 0; o >>= 1)
        v = fmaxf(v, __shfl_down_sync(0xffffffffu, v, o));
    int lane = threadIdx.x & 31, w = threadIdx.x >> 5;
    int nw = blockDim.x >> 5;
    if (lane == 0) sm_[w] = v;
    __syncthreads();
    if (w == 0) {
        v = (lane < nw) ? sm_[lane] : -1e30f;
        #pragma unroll
        for (int o = 16; o > 0; o >>= 1)
            v = fmaxf(v, __shfl_down_sync(0xffffffffu, v, o));
        if (lane == 0) sm_[0] = v;
    }
    __syncthreads();
    v = sm_[0];
    __syncthreads();
    return v;
}

__device__ __forceinline__ float blockReduceSum1(float v) {
    __shared__ float ss[32];
    #pragma unroll
    for (int o = 16; o > 0; o >>= 1)
        v += __shfl_down_sync(0xffffffffu, v, o);
    int lane = threadIdx.x & 31, w = threadIdx.x >> 5;
    int nw = blockDim.x >> 5;
    if (lane == 0) ss[w] = v;
    __syncthreads();
    if (w == 0) {
        v = (lane < nw) ? ss[lane] : 0.f;
        #pragma unroll
        for (int o = 16; o > 0; o >>= 1)
            v += __shfl_down_sync(0xffffffffu, v, o);
        if (lane == 0) ss[0] = v;
    }
    __syncthreads();
    v = ss[0];
    __syncthreads();
    return v;
}

__global__ void patchify_ln_kernel(const float* __restrict__ img,
                                   const float* __restrict__ gam,
                                   const float* __restrict__ bet) {
    int row = blockIdx.x;
    int b = row / NPAT, p = row % NPAT;
    int ph = p / 14, pw = p % 14;
    __shared__ float sh[PDIM];
    int t = threadIdx.x;
    float s = 0.f, sq = 0.f;
    for (int i = t; i < PDIM; i += 256) {
        int c  = i % 3;
        int pp = i / 3;
        int p1 = pp >> 4, p2 = pp & 15;
        float v = img[(((size_t)b * 3 + c) * 224 + ph * 16 + p1) * 224 + pw * 16 + p2];
        sh[i] = v;
        s += v; sq += v * v;
    }
    blockReduce2Sum(s, sq);
    float mean = s * (1.f / PDIM);
    float var  = sq * (1.f / PDIM) - mean * mean;
    float inv  = rsqrtf(var + LN_EPS);
    for (int i = t; i < PDIM; i += 256)
        g_xp[(size_t)row * PDIM + i] = (sh[i] - mean) * inv * gam[i] + bet[i];
}

template<bool ADDPOS>
__global__ void ln_kernel(float* __restrict__ x,
                          const float* __restrict__ gam,
                          const float* __restrict__ bet,
                          const float* __restrict__ pos) {
    size_t row = blockIdx.x;
    int t = threadIdx.x;
    float4 v = ((const float4*)(x + row * DMODEL))[t];
    float s  = v.x + v.y + v.z + v.w;
    float sq = v.x * v.x + v.y * v.y + v.z * v.z + v.w * v.w;
    blockReduce2Sum(s, sq);
    float mean = s * (1.f / DMODEL);
    float var  = sq * (1.f / DMODEL) - mean * mean;
    float inv  = rsqrtf(var + LN_EPS);
    float4 g4 = ((const float4*)gam)[t];
    float4 b4 = ((const float4*)bet)[t];
    float4 o;
    o.x = (v.x - mean) * inv * g4.x + b4.x;
    o.y = (v.y - mean) * inv * g4.y + b4.y;
    o.z = (v.z - mean) * inv * g4.z + b4.z;
    o.w = (v.w - mean) * inv * g4.w + b4.w;
    if (ADDPOS) {
        int n = (int)(row % NPAT);
        float4 p4 = ((const float4*)(pos + (size_t)n * DMODEL))[t];
        o.x += p4.x; o.y += p4.y; o.z += p4.z; o.w += p4.w;
    }
    ((float4*)(x + row * DMODEL))[t] = o;
}

// 3xTF32 GEMM — identical to the Round-4 champion.
template<bool TRANSB, bool BIAS, bool RESID>
__global__ __launch_bounds__(256, 1)
void gemm_tc(const float* __restrict__ A, const float* __restrict__ B,
             const float* __restrict__ bias, const float* __restrict__ resid,
             float* __restrict__ C, int M, int N, int K,
             int lda, int ldb, int ldc,
             long sA, long sB, long sC) {
    extern __shared__ float sm[];
    float* sa = sm;
    float* sb = sm + 8192;

    long z = blockIdx.z;
    A += z * sA; B += z * sB; C += z * sC;
    if (RESID) resid += z * sC;

    int tid = threadIdx.x;
    int lane = tid & 31, warp = tid >> 5;
    int wm = warp >> 2;
    int wn = warp & 3;
    int m0 = blockIdx.y * MT, n0 = blockIdx.x * NT;

    float4 acc[4][4];
    #pragma unroll
    for (int i = 0; i < 4; i++)
        #pragma unroll
        for (int j = 0; j < 4; j++)
            acc[i][j] = make_float4(0.f, 0.f, 0.f, 0.f);

    int nIter = (K + KTILE - 1) / KTILE;
    float ra[16], rb[16];

    auto loadTiles = [&](int k0) {
        #pragma unroll
        for (int i = 0; i < 16; i++) {
            int idx = tid + i * 256;
            int r = idx >> 5, c = idx & 31;
            int gm = m0 + r, gk = k0 + c;
            ra[i] = (gm < M && gk < K) ? A[(long)gm * lda + gk] : 0.f;
        }
        #pragma unroll
        for (int i = 0; i < 16; i++) {
            int idx = tid + i * 256;
            if (TRANSB) {
                int n = idx >> 5, k = idx & 31;
                int gn = n0 + n, gk = k0 + k;
                rb[i] = (gn < N && gk < K) ? B[(long)gn * ldb + gk] : 0.f;
            } else {
                int k = idx >> 7, n = idx & 127;
                int gk = k0 + k, gn = n0 + n;
                rb[i] = (gk < K && gn < N) ? B[(long)gk * ldb + gn] : 0.f;
            }
        }
    };

    auto storeTiles = [&](int buf) {
        float* pa = sa + buf * 4096;
        float* pb = sb + buf * 4096;
        #pragma unroll
        for (int i = 0; i < 16; i++) {
            int idx = tid + i * 256;
            int r = idx >> 5, c = idx & 31;
            int mi = r >> 4, rr = r & 15, ki = c >> 3, cc = c & 7;
            int ln_ = ((rr & 7) << 2) | (cc & 3);
            int j   = ((cc >> 2) << 1) | (rr >> 3);
            pa[((mi * 4 + ki) * 32 + ln_) * 4 + j] = ra[i];
        }
        #pragma unroll
        for (int i = 0; i < 16; i++) {
            int idx = tid + i * 256;
            int k, n;
            if (TRANSB) { n = idx >> 5; k = idx & 31; }
            else        { k = idx >> 7; n = idx & 127; }
            int ni = n >> 3, nn = n & 7, ki = k >> 3, kk = k & 7;
            int ln_ = (nn << 2) | (kk & 3);
            int j   = kk >> 2;
            pb[((ni * 4 + ki) * 32 + ln_) * 2 + j] = rb[i];
        }
    };

    loadTiles(0);
    storeTiles(0);
    __syncthreads();

    for (int it = 0; it < nIter; it++) {
        if (it + 1 < nIter) loadTiles((it + 1) * KTILE);

        int buf = it & 1;
        const float* pa = sa + buf * 4096;
        const float* pb = sb + buf * 4096;

        #pragma unroll
        for (int ki = 0; ki < 4; ki++) {
            float4 ah[4], al[4];
            float2 bh[4], bl[4];
            #pragma unroll
            for (int mi = 0; mi < 4; mi++) {
                int mig = wm * 4 + mi;
                float4 v = *(const float4*)&pa[((mig * 4 + ki) * 32 + lane) * 4];
                ah[mi].x = tf32r(v.x); al[mi].x = tf32r(v.x - ah[mi].x);
                ah[mi].y = tf32r(v.y); al[mi].y = tf32r(v.y - ah[mi].y);
                ah[mi].z = tf32r(v.z); al[mi].z = tf32r(v.z - ah[mi].z);
                ah[mi].w = tf32r(v.w); al[mi].w = tf32r(v.w - ah[mi].w);
            }
            #pragma unroll
            for (int ni = 0; ni < 4; ni++) {
                int nig = wn * 4 + ni;
                float2 v = *(const float2*)&pb[((nig * 4 + ki) * 32 + lane) * 2];
                bh[ni].x = tf32r(v.x); bl[ni].x = tf32r(v.x - bh[ni].x);
                bh[ni].y = tf32r(v.y); bl[ni].y = tf32r(v.y - bh[ni].y);
            }
            #pragma unroll
            for (int mi = 0; mi < 4; mi++)
                #pragma unroll
                for (int ni = 0; ni < 4; ni++) {
                    mma8(acc[mi][ni], al[mi], bh[ni]);
                    mma8(acc[mi][ni], ah[mi], bl[ni]);
                    mma8(acc[mi][ni], ah[mi], bh[ni]);
                }
        }

        if (it + 1 < nIter) storeTiles(buf ^ 1);
        __syncthreads();
    }

    int g = lane >> 2, t4 = lane & 3;
    #pragma unroll
    for (int mi = 0; mi < 4; mi++) {
        int row = m0 + (wm * 4 + mi) * 16 + g;
        #pragma unroll
        for (int ni = 0; ni < 4; ni++) {
            int col = n0 + (wn * 4 + ni) * 8 + t4 * 2;
            float4 v = acc[mi][ni];
            if (BIAS) {
                if (col < N)     { v.x += bias[col];     v.z += bias[col]; }
                if (col + 1 < N) { v.y += bias[col + 1]; v.w += bias[col + 1]; }
            }
            if (row < M) {
                long o = (long)row * ldc + col;
                if (col < N)     C[o]     = RESID ? v.x + resid[o]     : v.x;
                if (col + 1 < N) C[o + 1] = RESID ? v.y + resid[o + 1] : v.y;
            }
            if (row + 8 < M) {
                long o = (long)(row + 8) * ldc + col;
                if (col < N)     C[o]     = RESID ? v.z + resid[o]     : v.z;
                if (col + 1 < N) C[o + 1] = RESID ? v.w + resid[o + 1] : v.w;
            }
        }
    }
}

__global__ void softmax_kernel(float* __restrict__ S) {
    size_t row = blockIdx.x;
    float* p = S + row * NPAT;
    int t = threadIdx.x;
    float v = (t < NPAT) ? p[t] * ATT_SCALE : -1e30f;
    float m = blockReduceMax(v);
    float e = (t < NPAT) ? __expf(v - m) : 0.f;
    float s = blockReduceSum1(e);
    if (t < NPAT) p[t] = e / s;
}

__global__ void pool_kernel() {
    int i = blockIdx.x * 256 + threadIdx.x;
    if (i >= CB * DMODEL) return;
    int b = i / DMODEL, d = i % DMODEL;
    const float* p = g_x + (size_t)b * NPAT * DMODEL + d;
    float s = 0.f;
    for (int n = 0; n < NPAT; n++) s += p[(size_t)n * DMODEL];
    g_pool[i] = s * (1.f / NPAT);
}

extern "C" void kernel_launch(void* const* d_in, const int* in_sizes, int n_in,
                              void* d_out, int out_size) {
    const float* image   = (const float*)d_in[0];
    const float* pos_emb = (const float*)d_in[1];
    const float* ln_p_g  = (const float*)d_in[2];
    const float* ln_p_b  = (const float*)d_in[3];
    const float* W_emb   = (const float*)d_in[4];
    const float* b_emb   = (const float*)d_in[5];
    const float* ln_e_g  = (const float*)d_in[6];
    const float* ln_e_b  = (const float*)d_in[7];
    const float* WV      = (const float*)d_in[8];
    const float* WK      = (const float*)d_in[9];
    const float* WQ      = (const float*)d_in[10];
    const float* ln_g    = (const float*)d_in[11];
    const float* ln_b    = (const float*)d_in[12];
    const float* W_last  = (const float*)d_in[13];
    const float* b_last  = (const float*)d_in[14];
    float* out = (float*)d_out;

    float *xp, *x, *t, *Mw, *fw, *A, *pool;
    cudaGetSymbolAddress((void**)&xp,   g_xp);
    cudaGetSymbolAddress((void**)&x,    g_x);
    cudaGetSymbolAddress((void**)&t,    g_t);
    cudaGetSymbolAddress((void**)&Mw,   g_M);
    cudaGetSymbolAddress((void**)&fw,   g_fw);
    cudaGetSymbolAddress((void**)&A,    g_A);
    cudaGetSymbolAddress((void**)&pool, g_pool);

    cudaFuncSetAttribute(gemm_tc<false, true,  false>,
                         cudaFuncAttributeMaxDynamicSharedMemorySize, GEMM_SMEM);
    cudaFuncSetAttribute(gemm_tc<false, false, false>,
                         cudaFuncAttributeMaxDynamicSharedMemorySize, GEMM_SMEM);
    cudaFuncSetAttribute(gemm_tc<true,  false, false>,
                         cudaFuncAttributeMaxDynamicSharedMemorySize, GEMM_SMEM);
    cudaFuncSetAttribute(gemm_tc<false, false, true>,
                         cudaFuncAttributeMaxDynamicSharedMemorySize, GEMM_SMEM);

    // second stream + fork/join events (host-side resources; no device allocs)
    cudaStream_t s2;
    cudaStreamCreateWithFlags(&s2, cudaStreamNonBlocking);
    cudaEvent_t evFork, evM, evLN[NDEPTH], evFW[NDEPTH];
    cudaEventCreateWithFlags(&evFork, cudaEventDisableTiming);
    cudaEventCreateWithFlags(&evM,    cudaEventDisableTiming);
    for (int l = 0; l < NDEPTH; l++) {
        cudaEventCreateWithFlags(&evLN[l], cudaEventDisableTiming);
        cudaEventCreateWithFlags(&evFW[l], cudaEventDisableTiming);
    }

    // fork s2 off the capture (default) stream
    cudaEventRecord(evFork, 0);
    cudaStreamWaitEvent(s2, evFork, 0);

    // 0) M = WQ @ WK^T on s2, overlapped with patchify/embed on s0
    gemm_tc<true, false, false><<<dim3(8, 8, 1), 256, GEMM_SMEM, s2>>>(
        WQ, WK, nullptr, nullptr, Mw, DMODEL, DMODEL, DMODEL, DMODEL, DMODEL, DMODEL, 0, 0, 0);
    cudaEventRecord(evM, s2);

    // 1) patchify + LN_p
    patchify_ln_kernel<<<NROWS, 256>>>(image, ln_p_g, ln_p_b);

    // 2) embed
    gemm_tc<false, true, false><<<dim3(8, 98, 1), 256, GEMM_SMEM>>>(
        xp, W_emb, b_emb, nullptr, x, NROWS, DMODEL, PDIM, PDIM, DMODEL, DMODEL, 0, 0, 0);

    // 3) LN_e + pos
    ln_kernel<true><<<NROWS, 256>>>(x, ln_e_g, ln_e_b, pos_emb);

    // s0 must see M before the first t-GEMM
    cudaStreamWaitEvent(0, evM, 0);

    for (int l = 0; l < NDEPTH; l++) {
        // x <- LN(x)
        ln_kernel<false><<<NROWS, 256>>>(x, ln_g, ln_b, nullptr);
        cudaEventRecord(evLN[l], 0);

        // fw = per-head x @ WV on s2 (depends only on LN(x))
        cudaStreamWaitEvent(s2, evLN[l], 0);
        gemm_tc<false, false, false><<<dim3(1, 784, 1), 256, GEMM_SMEM, s2>>>(
            x, WV, nullptr, nullptr, fw, NROWS * NHEADS, VD, VD, VD, VD, VD, 0, 0, 0);
        cudaEventRecord(evFW[l], s2);

        // t = x @ M on s0 (fused q,k)
        gemm_tc<false, false, false><<<dim3(8, 98, 1), 256, GEMM_SMEM>>>(
            x, Mw, nullptr, nullptr, t, NROWS, DMODEL, DMODEL, DMODEL, DMODEL, DMODEL, 0, 0, 0);

        // scores A = t @ x^T per batch
        gemm_tc<true, false, false><<<dim3(2, 2, CB), 256, GEMM_SMEM>>>(
            t, x, nullptr, nullptr, A, NPAT, NPAT, DMODEL, DMODEL, DMODEL, NPAT,
            (long)NPAT * DMODEL, (long)NPAT * DMODEL, (long)NPAT * NPAT);

        softmax_kernel<<<NROWS, 256>>>(A);

        // join: AV needs fw
        cudaStreamWaitEvent(0, evFW[l], 0);

        // x = A @ fw + x
        gemm_tc<false, false, true><<<dim3(8, 2, CB), 256, GEMM_SMEM>>>(
            A, fw, nullptr, x, x, NPAT, DMODEL, NPAT, NPAT, DMODEL, DMODEL,
            (long)NPAT * NPAT, (long)NPAT * DMODEL, (long)NPAT * DMODEL);
    }

    pool_kernel<<<(CB * DMODEL + 255) / 256, 256>>>();

    gemm_tc<false, true, false><<<dim3(8, 1, 1), 256, GEMM_SMEM>>>(
        pool, W_last, b_last, nullptr, out, CB, NCLS, DMODEL, DMODEL, NCLS, NCLS, 0, 0, 0);
}